// round 2
// baseline (speedup 1.0000x reference)
#include <cuda_runtime.h>
#include <math.h>

#define HEADS 12
#define HD 64
#define DIMC 768
#define NB 4
#define NN 1024
#define LDQKV (3 * DIMC)
#define ATT_SCALE 0.125f

// ---------------- scratch (static device globals; no runtime allocation) ----------------
__device__ float g_qkv[(size_t)NB * NN * 3 * DIMC];       // [B,N,3C]      37.7 MB
__device__ float g_S[(size_t)NB * HEADS * NN * NN];       // scores, then mixed attention A (in-place)  201 MB
__device__ float g_Av[(size_t)NB * HEADS * NN * HD];      // A @ v         12.6 MB
__device__ float g_O[(size_t)NB * NN * DIMC];             // [B,N,C] pre-transposed  12.6 MB

// ---------------- 128x128x8 NT sgemm tile (C = alpha * A @ B^T + bias) ----------------
// A: [M,K] row-major (lda), B: [N,K] row-major (ldb), C: [M,N] row-major (ldc).
// Requires M,N multiples of 128, K multiple of 8, lda/ldb multiples of 4.
__device__ __forceinline__ void sgemm_nt_128(
    const float* __restrict__ A, int lda,
    const float* __restrict__ B, int ldb,
    float* __restrict__ C, int ldc,
    int K, float alpha, const float* __restrict__ bias)
{
    __shared__ float As[8][128];
    __shared__ float Bs[8][128];
    const int tid = threadIdx.x;
    const int row0 = blockIdx.y * 128;
    const int col0 = blockIdx.x * 128;

    const int lr = tid >> 1;          // 0..127 (tile row/col for loading)
    const int lp = (tid & 1) << 2;    // 0 or 4 (k sub-offset)
    const float* Ap = A + (size_t)(row0 + lr) * lda + lp;
    const float* Bp = B + (size_t)(col0 + lr) * ldb + lp;

    const int rt = (tid >> 4) << 3;   // thread micro-tile row
    const int ct = (tid & 15) << 3;   // thread micro-tile col

    float acc[8][8];
#pragma unroll
    for (int i = 0; i < 8; i++)
#pragma unroll
        for (int j = 0; j < 8; j++) acc[i][j] = 0.f;

    for (int k0 = 0; k0 < K; k0 += 8) {
        float4 av = *(const float4*)(Ap + k0);
        float4 bv = *(const float4*)(Bp + k0);
        As[lp + 0][lr] = av.x; As[lp + 1][lr] = av.y;
        As[lp + 2][lr] = av.z; As[lp + 3][lr] = av.w;
        Bs[lp + 0][lr] = bv.x; Bs[lp + 1][lr] = bv.y;
        Bs[lp + 2][lr] = bv.z; Bs[lp + 3][lr] = bv.w;
        __syncthreads();
#pragma unroll
        for (int kk = 0; kk < 8; kk++) {
            float a[8], b[8];
#pragma unroll
            for (int i = 0; i < 8; i++) a[i] = As[kk][rt + i];
#pragma unroll
            for (int j = 0; j < 8; j++) b[j] = Bs[kk][ct + j];
#pragma unroll
            for (int i = 0; i < 8; i++)
#pragma unroll
                for (int j = 0; j < 8; j++)
                    acc[i][j] = fmaf(a[i], b[j], acc[i][j]);
        }
        __syncthreads();
    }

    float bj[8];
#pragma unroll
    for (int j = 0; j < 8; j++) bj[j] = bias ? bias[col0 + ct + j] : 0.f;
#pragma unroll
    for (int i = 0; i < 8; i++) {
        float* Cp = C + (size_t)(row0 + rt + i) * ldc + col0 + ct;
        float4 v0, v1;
        v0.x = fmaf(acc[i][0], alpha, bj[0]);
        v0.y = fmaf(acc[i][1], alpha, bj[1]);
        v0.z = fmaf(acc[i][2], alpha, bj[2]);
        v0.w = fmaf(acc[i][3], alpha, bj[3]);
        v1.x = fmaf(acc[i][4], alpha, bj[4]);
        v1.y = fmaf(acc[i][5], alpha, bj[5]);
        v1.z = fmaf(acc[i][6], alpha, bj[6]);
        v1.w = fmaf(acc[i][7], alpha, bj[7]);
        *(float4*)(Cp + 0) = v0;
        *(float4*)(Cp + 4) = v1;
    }
}

// ---------------- 64x64 NN gemm tile (C_tile = A[m0:m0+64, :K] @ B[:K, 0:64]) ----------------
// A row-major (lda), B row-major (ldb). K multiple of 16.
__device__ __forceinline__ void gemm_nn_64(
    const float* __restrict__ A, int lda,
    const float* __restrict__ B, int ldb,
    int K, int m0, float (&acc)[4][4])
{
    __shared__ float As[16][64];
    __shared__ float Bs[16][64];
    const int tid = threadIdx.x;
    const int ar = tid >> 2;          // 0..63 row of A tile
    const int ap = (tid & 3) << 2;    // k part 0,4,8,12
    const int br = tid >> 4;          // 0..15 k row of B tile
    const int bp = (tid & 15) << 2;   // col part
    const int rt = (tid >> 4) << 2;
    const int ct = (tid & 15) << 2;

#pragma unroll
    for (int i = 0; i < 4; i++)
#pragma unroll
        for (int j = 0; j < 4; j++) acc[i][j] = 0.f;

    const float* Ap = A + (size_t)(m0 + ar) * lda + ap;

    for (int k0 = 0; k0 < K; k0 += 16) {
        float4 av = *(const float4*)(Ap + k0);
        float4 bv = *(const float4*)(B + (size_t)(k0 + br) * ldb + bp);
        As[ap + 0][ar] = av.x; As[ap + 1][ar] = av.y;
        As[ap + 2][ar] = av.z; As[ap + 3][ar] = av.w;
        Bs[br][bp + 0] = bv.x; Bs[br][bp + 1] = bv.y;
        Bs[br][bp + 2] = bv.z; Bs[br][bp + 3] = bv.w;
        __syncthreads();
#pragma unroll
        for (int kk = 0; kk < 16; kk++) {
            float a[4], b[4];
#pragma unroll
            for (int i = 0; i < 4; i++) a[i] = As[kk][rt + i];
#pragma unroll
            for (int j = 0; j < 4; j++) b[j] = Bs[kk][ct + j];
#pragma unroll
            for (int i = 0; i < 4; i++)
#pragma unroll
                for (int j = 0; j < 4; j++)
                    acc[i][j] = fmaf(a[i], b[j], acc[i][j]);
        }
        __syncthreads();
    }
}

// ---------------- kernels ----------------

// qkv = x @ qkv_w^T   [4096,768] x [2304,768]^T -> [4096,2304]
__global__ void __launch_bounds__(256) k_qkv(const float* __restrict__ x,
                                             const float* __restrict__ w)
{
    sgemm_nt_128(x, DIMC, w, DIMC, g_qkv, LDQKV, DIMC, 1.f, nullptr);
}

// S[b,h] = SCALE * q_h @ k_h^T, 48 batches of [1024,64]x[64,1024]
__global__ void __launch_bounds__(256) k_scores()
{
    const int z = blockIdx.z;
    const int b = z / HEADS, h = z % HEADS;
    const float* q = g_qkv + (size_t)b * NN * LDQKV + h * HD;
    const float* k = q + DIMC;
    float* S = g_S + (size_t)z * NN * NN;
    sgemm_nt_128(q, LDQKV, k, LDQKV, S, NN, HD, ATT_SCALE, nullptr);
}

// Fused: pre-softmax head mix (L) -> softmax over m -> post-softmax head mix (W).
// One block per (b,n) row; operates on all 12 heads in smem; writes A in-place over S.
__global__ void __launch_bounds__(256) k_mix(const float* __restrict__ Lw,
                                             const float* __restrict__ Lb,
                                             const float* __restrict__ Ww,
                                             const float* __restrict__ Wb)
{
    extern __shared__ float sm[];  // [12][1024]
    __shared__ float sL[144], sW[144], sbl[12], sbw[12];
    __shared__ float red[12][8];
    __shared__ float gmax[12], ginv[12];

    const int tid = threadIdx.x;
    const int b = blockIdx.x >> 10;
    const int n = blockIdx.x & 1023;

    if (tid < 144) { sL[tid] = Lw[tid]; sW[tid] = Ww[tid]; }
    if (tid < 12)  { sbl[tid] = Lb[tid]; sbw[tid] = Wb[tid]; }

    float* Sbase = g_S + (size_t)b * HEADS * NN * NN + (size_t)n * NN;

    for (int idx = tid; idx < HEADS * NN; idx += 256) {
        int h = idx >> 10, m = idx & 1023;
        sm[idx] = Sbase[(size_t)h * NN * NN + m];
    }
    __syncthreads();

    // pass 1: L-mix (in-place per column) + per-head running max
    float lred[12];
#pragma unroll
    for (int g = 0; g < 12; g++) lred[g] = -1e30f;
    for (int m = tid; m < NN; m += 256) {
        float s[12];
#pragma unroll
        for (int h = 0; h < 12; h++) s[h] = sm[(h << 10) + m];
#pragma unroll
        for (int g = 0; g < 12; g++) {
            float t = sbl[g];
#pragma unroll
            for (int h = 0; h < 12; h++) t = fmaf(sL[g * 12 + h], s[h], t);
            sm[(g << 10) + m] = t;
            lred[g] = fmaxf(lred[g], t);
        }
    }
    const int lane = tid & 31, wrp = tid >> 5;
#pragma unroll
    for (int g = 0; g < 12; g++) {
        float v = lred[g];
#pragma unroll
        for (int o = 16; o; o >>= 1) v = fmaxf(v, __shfl_xor_sync(0xffffffffu, v, o));
        if (lane == 0) red[g][wrp] = v;
    }
    __syncthreads();
    if (tid < 12) {
        float v = red[tid][0];
#pragma unroll
        for (int w = 1; w < 8; w++) v = fmaxf(v, red[tid][w]);
        gmax[tid] = v;
    }
    __syncthreads();

    // pass 2: exp + per-head sum
#pragma unroll
    for (int g = 0; g < 12; g++) lred[g] = 0.f;
    for (int m = tid; m < NN; m += 256) {
#pragma unroll
        for (int g = 0; g < 12; g++) {
            float e = __expf(sm[(g << 10) + m] - gmax[g]);
            sm[(g << 10) + m] = e;
            lred[g] += e;
        }
    }
#pragma unroll
    for (int g = 0; g < 12; g++) {
        float v = lred[g];
#pragma unroll
        for (int o = 16; o; o >>= 1) v += __shfl_xor_sync(0xffffffffu, v, o);
        if (lane == 0) red[g][wrp] = v;
    }
    __syncthreads();
    if (tid < 12) {
        float v = red[tid][0];
#pragma unroll
        for (int w = 1; w < 8; w++) v += red[tid][w];
        ginv[tid] = 1.f / v;
    }
    __syncthreads();

    // pass 3: normalize + W-mix, write back in place (A overwrites S)
    for (int m = tid; m < NN; m += 256) {
        float p[12];
#pragma unroll
        for (int h = 0; h < 12; h++) p[h] = sm[(h << 10) + m] * ginv[h];
#pragma unroll
        for (int g = 0; g < 12; g++) {
            float a = sbw[g];
#pragma unroll
            for (int h = 0; h < 12; h++) a = fmaf(sW[g * 12 + h], p[h], a);
            Sbase[(size_t)g * NN * NN + m] = a;
        }
    }
}

// Av[b,h] = A[b,h] @ v[b,h]   ([1024,1024] @ [1024,64])
__global__ void __launch_bounds__(256) k_av()
{
    const int z = blockIdx.z;
    const int b = z / HEADS, h = z % HEADS;
    const int m0 = blockIdx.x * 64;
    const float* A = g_S + (size_t)z * NN * NN;
    const float* V = g_qkv + (size_t)b * NN * LDQKV + 2 * DIMC + h * HD;
    float acc[4][4];
    gemm_nn_64(A, NN, V, LDQKV, NN, m0, acc);
    const int tid = threadIdx.x;
    const int rt = (tid >> 4) << 2, ct = (tid & 15) << 2;
    float* out = g_Av + (size_t)z * NN * HD;
#pragma unroll
    for (int i = 0; i < 4; i++)
#pragma unroll
        for (int j = 0; j < 4; j++)
            out[(size_t)(m0 + rt + i) * HD + ct + j] = acc[i][j];
}

// O[b,n,h,d] = (1-2*lam_h)*Av + 3*lam_h*(A @ Av)   — written pre-transposed to [B,N,C]
__global__ void __launch_bounds__(256) k_aav(const float* __restrict__ lamb)
{
    const int z = blockIdx.z;
    const int b = z / HEADS, h = z % HEADS;
    const int m0 = blockIdx.x * 64;
    const float* A = g_S + (size_t)z * NN * NN;
    const float* Bv = g_Av + (size_t)z * NN * HD;
    float acc[4][4];
    gemm_nn_64(A, NN, Bv, HD, NN, m0, acc);
    const float lam = lamb[h];
    const float c1 = 1.f - 2.f * lam;
    const float c3 = 3.f * lam;
    const int tid = threadIdx.x;
    const int rt = (tid >> 4) << 2, ct = (tid & 15) << 2;
#pragma unroll
    for (int i = 0; i < 4; i++) {
        const int nrow = m0 + rt + i;
#pragma unroll
        for (int j = 0; j < 4; j++) {
            const int d = ct + j;
            float av = g_Av[(size_t)z * NN * HD + (size_t)nrow * HD + d];
            g_O[((size_t)b * NN + nrow) * DIMC + h * HD + d] = c1 * av + c3 * acc[i][j];
        }
    }
}

// Y = O @ Wout^T + bout   [4096,768] x [768,768]^T
__global__ void __launch_bounds__(256) k_out(const float* __restrict__ w,
                                             const float* __restrict__ bias,
                                             float* __restrict__ out)
{
    sgemm_nt_128(g_O, DIMC, w, DIMC, out, DIMC, DIMC, 1.f, bias);
}

// ---------------- launch ----------------
extern "C" void kernel_launch(void* const* d_in, const int* in_sizes, int n_in,
                              void* d_out, int out_size)
{
    (void)in_sizes; (void)n_in; (void)out_size;
    const float* x      = (const float*)d_in[0];
    const float* qkv_w  = (const float*)d_in[1];
    const float* Lw     = (const float*)d_in[2];
    const float* Lb     = (const float*)d_in[3];
    const float* Ww     = (const float*)d_in[4];
    const float* Wb     = (const float*)d_in[5];
    const float* lamb   = (const float*)d_in[6];
    const float* Wout   = (const float*)d_in[7];
    const float* bout   = (const float*)d_in[8];
    float* out = (float*)d_out;

    // k_mix needs 48KB dynamic + ~1.6KB static smem: opt in above the 48KB
    // default. Host-side attribute set, not a stream op — capture-safe,
    // deterministic, idempotent.
    cudaFuncSetAttribute(k_mix, cudaFuncAttributeMaxDynamicSharedMemorySize,
                         HEADS * NN * sizeof(float));

    // 1) qkv = x @ qkv_w^T
    k_qkv<<<dim3(LDQKV / 128, (NB * NN) / 128), 256>>>(x, qkv_w);
    // 2) scores (scaled)
    k_scores<<<dim3(NN / 128, NN / 128, NB * HEADS), 256>>>();
    // 3) fused L-mix -> softmax -> W-mix (in-place on g_S)
    k_mix<<<NB * NN, 256, HEADS * NN * sizeof(float)>>>(Lw, Lb, Ww, Wb);
    // 4) Av = A @ v
    k_av<<<dim3(NN / 64, 1, NB * HEADS), 256>>>();
    // 5) O = (1-2λ)Av + 3λ A@Av, pre-transposed to [B,N,C]
    k_aav<<<dim3(NN / 64, 1, NB * HEADS), 256>>>(lamb);
    // 6) final projection + bias
    k_out<<<dim3(DIMC / 128, (NB * NN) / 128), 256>>>(Wout, bout, out);
}